// round 16
// baseline (speedup 1.0000x reference)
#include <cuda_runtime.h>
#include <cuda_bf16.h>

// p1, p2: [B=2, C=32, D=96, H=96, W=96] fp32
// pool to S=8 (cells 12^3), L = 512 tokens, C = 32 channels.
// loss = (1/(L^2 B)) * sum_b [ ||Ga||F^2 + ||Gb||F^2 - 2||Gx||F^2 ]
// with G = (normalized tokens)^T (normalized tokens); normalization folded
// into the Gram loop as per-token weights w_l = 1/n_l.
//
// Single launch, 8224 blocks:
//   bid <  8192 : pool block with the PROVEN R13 bid decode (ph,pd low bits
//                 -> concurrent blocks stay inside a few contiguous channel
//                 planes; TLB/L2-friendly). Ends with release fence (8 writer
//                 threads) + one ticket on its chunk counter.
//   bid >= 8192 : 32 waiter blocks (dispatched last). Each spins on its
//                 chunk counter, computes that chunk's partial Grams,
//                 atomically accumulates; last done-ticket block finalizes
//                 and resets all state for graph replay.

#define BATCH 2
#define CH    32
#define DIM   96
#define LTOK  512
#define BLK   12
#define EPS   1e-8f
#define LSTR  33
#define NCHUNK 32
#define CONTRIB 256          // 2 tensors x 32 ch x 4 ph per chunk
#define POOL_BLOCKS 8192

// pooled tokens token-major: [tensor(2)][b(2)][l(512)][c(32)]
__device__ float g_pooled[2 * BATCH * LTOK * CH];
// Grams: [b(2)][g(3: aa, bb, ab)][i(32)][j(32)] (zero-init; finalizer re-zeroes)
__device__ float g_gram[BATCH * 3 * CH * CH];
__device__ unsigned int g_chunk_cnt[NCHUNK];   // reset by its waiter
__device__ unsigned int g_done;                // reset by finalizer

__global__ __launch_bounds__(96, 20)
void fused_kernel(const float* __restrict__ p1,
                  const float* __restrict__ p2,
                  float* __restrict__ out)
{
    const int bid = blockIdx.x;
    const int tid = threadIdx.x;

    __shared__ float sh[2 * CH * LSTR];   // sim: raw tokens [t][c][l] (8.4 KB)
    __shared__ float shinv[2 * 32];       // sim: per-token 1/norm
    __shared__ float shred[96];           // pool: partial sums
    __shared__ float wsum[3];
    __shared__ unsigned int s_flag;

    if (bid < POOL_BLOCKS) {
        // ---------------- pool path: EXACT R13 decode + body --------------
        const int ph = bid & 7;
        const int pd = (bid >> 3) & 7;
        const int c  = (bid >> 6) & 31;
        const int b  = (bid >> 11) & 1;
        const int t  = bid >> 12;

        const float* __restrict__ in = (t == 0) ? p1 : p2;
        const int f4 = tid % 24;    // w = 4*f4
        const int rs = tid / 24;    // d chunk [3rs, 3rs+3)

        const float* __restrict__ base =
            in + ((size_t)(b * CH + c)) * (DIM * DIM * DIM)
               + (size_t)(pd * BLK + 3 * rs) * (DIM * DIM)
               + (size_t)ph * BLK * DIM
               + f4 * 4;

        float acc = 0.0f;
        #pragma unroll
        for (int d2 = 0; d2 < 3; ++d2) {
            #pragma unroll
            for (int h = 0; h < 12; ++h) {
                const float4 v = __ldcs(reinterpret_cast<const float4*>(
                    base + d2 * (DIM * DIM) + h * DIM));
                acc += (v.x + v.y) + (v.z + v.w);
            }
        }

        shred[tid] = acc;
        __syncthreads();

        if (tid < 8) {
            float s = 0.0f;
            #pragma unroll
            for (int r2 = 0; r2 < 4; ++r2)
                #pragma unroll
                for (int j = 0; j < 3; ++j)
                    s += shred[r2 * 24 + tid * 3 + j];
            const int l = pd * 64 + ph * 8 + tid;
            g_pooled[(((size_t)t * BATCH + b) * LTOK + l) * CH + c] =
                s * (1.0f / (BLK * BLK * BLK));
            __threadfence();   // release pooled write before ticket
        }
        __syncthreads();
        if (tid == 0)
            atomicAdd(&g_chunk_cnt[b * 16 + pd * 2 + (ph >> 2)], 1u);
        return;
    }

    // ---------------- waiter path: one block per 32-token chunk -----------
    const int sid = bid - POOL_BLOCKS;      // == cid, 0..31
    const int b   = sid >> 4;
    const int l0  = (sid & 15) * 32;        // = pd*64 + phg*32

    if (tid == 0) {
        while (atomicAdd(&g_chunk_cnt[sid], 0u) < CONTRIB)
            __nanosleep(128);
        atomicExch(&g_chunk_cnt[sid], 0u);   // reset for next replay
        __threadfence();                      // acquire contributors' writes
    }
    __syncthreads();

    // load raw tokens (channel-major, stride 33) + per-token inverse norms
    if (tid < 64) {
        const int tt = tid >> 5;             // tensor
        const int l  = tid & 31;
        const float* __restrict__ src =
            g_pooled + (((size_t)tt * BATCH + b) * LTOK + l0 + l) * CH;
        float s = 0.0f;
        #pragma unroll
        for (int k = 0; k < 8; ++k) {
            const float4 v = __ldcg(reinterpret_cast<const float4*>(src + 4 * k));
            s += v.x * v.x + v.y * v.y + v.z * v.z + v.w * v.w;
            float* d = sh + tt * CH * LSTR + (4 * k) * LSTR + l;
            d[0 * LSTR] = v.x;  d[1 * LSTR] = v.y;
            d[2 * LSTR] = v.z;  d[3 * LSTR] = v.w;
        }
        shinv[tt * 32 + l] = rsqrtf(fmaxf(s, EPS));
    }
    __syncthreads();

    // Grams: 3 warps = 3 grams (aa, bb, ab); lane = output row i.
    // G_ij += sum_l (P[i][l]*w_l) * Q[j][l],  w_l = invP[l]*invQ[l].
    {
        const int g = tid >> 5;   // 0..2
        const int i = tid & 31;
        const float* __restrict__ P  = sh    + ((g == 1) ? CH * LSTR : 0);
        const float* __restrict__ Q  = sh    + ((g == 0) ? 0 : CH * LSTR);
        const float* __restrict__ wP = shinv + ((g == 1) ? 32 : 0);
        const float* __restrict__ wQ = shinv + ((g == 0) ? 0 : 32);
        float* __restrict__ dst = g_gram + (((b * 3 + g) << 10) + (i << 5));

        #pragma unroll
        for (int jg = 0; jg < 4; ++jg) {
            float a0 = 0, a1 = 0, a2 = 0, a3 = 0, a4 = 0, a5 = 0, a6 = 0, a7 = 0;
            #pragma unroll 8
            for (int l = 0; l < 32; ++l) {
                const float p = P[i * LSTR + l] * (wP[l] * wQ[l]);
                const float* q = Q + (jg * 8) * LSTR + l;
                a0 += p * q[0 * LSTR];  a1 += p * q[1 * LSTR];
                a2 += p * q[2 * LSTR];  a3 += p * q[3 * LSTR];
                a4 += p * q[4 * LSTR];  a5 += p * q[5 * LSTR];
                a6 += p * q[6 * LSTR];  a7 += p * q[7 * LSTR];
            }
            atomicAdd(&dst[jg * 8 + 0], a0);  atomicAdd(&dst[jg * 8 + 1], a1);
            atomicAdd(&dst[jg * 8 + 2], a2);  atomicAdd(&dst[jg * 8 + 3], a3);
            atomicAdd(&dst[jg * 8 + 4], a4);  atomicAdd(&dst[jg * 8 + 5], a5);
            atomicAdd(&dst[jg * 8 + 6], a6);  atomicAdd(&dst[jg * 8 + 7], a7);
        }
    }

    // done ticket -> last chunk block finalizes
    __threadfence();
    __syncthreads();
    if (tid == 0)
        s_flag = (atomicAdd(&g_done, 1u) == NCHUNK - 1) ? 1u : 0u;
    __syncthreads();
    if (!s_flag) return;

    __threadfence();   // acquire all gram atomics

    // loss = sum_b ( ||Gaa||^2 + ||Gbb||^2 - 2||Gab||^2 ) / (L^2 * B)
    float local = 0.0f;
    const float4* __restrict__ gv = reinterpret_cast<const float4*>(g_gram);
    #pragma unroll
    for (int k = 0; k < 16; ++k) {                 // 1536 float4 / 96 threads
        const int i4 = tid + k * 96;
        const int g  = (i4 >> 8) % 3;              // 256 float4 per gram
        const float w = (g == 2) ? -2.0f : 1.0f;
        const float4 v = __ldcg(&gv[i4]);
        local += w * (v.x * v.x + v.y * v.y + v.z * v.z + v.w * v.w);
    }
    #pragma unroll
    for (int off = 16; off > 0; off >>= 1)
        local += __shfl_xor_sync(0xFFFFFFFFu, local, off);
    if ((tid & 31) == 0) wsum[tid >> 5] = local;
    __syncthreads();
    if (tid == 0) {
        out[0] = (wsum[0] + wsum[1] + wsum[2]) *
                 (1.0f / ((float)LTOK * (float)LTOK * (float)BATCH));
        g_done = 0u;                                // reset for next replay
    }
    __syncthreads();                                // reads done before zeroing

    // re-zero gram accumulator for next replay
    const float4 z = make_float4(0.f, 0.f, 0.f, 0.f);
    float4* __restrict__ gz = reinterpret_cast<float4*>(g_gram);
    #pragma unroll
    for (int k = 0; k < 16; ++k)
        gz[tid + k * 96] = z;
}

// ---------------------------------------------------------------------------
extern "C" void kernel_launch(void* const* d_in, const int* in_sizes, int n_in,
                              void* d_out, int out_size)
{
    const float* p1 = (const float*)d_in[0];
    const float* p2 = (const float*)d_in[1];
    float* out = (float*)d_out;

    fused_kernel<<<POOL_BLOCKS + NCHUNK, 96>>>(p1, p2, out);
}

// round 17
// speedup vs baseline: 1.3679x; 1.3679x over previous
#include <cuda_runtime.h>
#include <cuda_bf16.h>

// p1, p2: [B=2, C=32, D=96, H=96, W=96] fp32
// pool to S=8 (cells 12^3), L = 512 tokens, C = 32 channels.
// loss = (1/(L^2 B)) * sum_b [ ||Ga||F^2 + ||Gb||F^2 - 2||Gx||F^2 ]
// with G = (normalized tokens)^T (normalized tokens).
// Two kernels: kernel boundary provides all ordering (NO fences in pool —
// gpu-scope fences emit CCTL.IVALL and destroy the streaming pipeline).

#define BATCH 2
#define CH    32
#define DIM   96
#define LTOK  512
#define BLK   12
#define EPS   1e-8f

// pooled tokens token-major: [tensor(2)][b(2)][l(512)][c(32)]
__device__ float g_pooled[2 * BATCH * LTOK * CH];
// partial Grams: [b(2)][g(3: aa, bb, ab)][i(32)][j(32)]
__device__ float g_gram[BATCH * 3 * CH * CH];
__device__ unsigned int g_cnt;

// ---------------------------------------------------------------------------
// Kernel 1: pooling — byte-identical to the proven 65.3us version.
// One block per (tensor, b, c, pd, ph); 96 threads; 36 affine-offset LDG.128
// per thread, streaming hint. Block 0 zeroes gram buffer + counter.
// ---------------------------------------------------------------------------
__global__ __launch_bounds__(96) void pool_kernel(const float* __restrict__ p1,
                                                  const float* __restrict__ p2)
{
    const int bid = blockIdx.x;
    if (bid == 0) {
        for (int i = threadIdx.x; i < BATCH * 3 * CH * CH; i += 96)
            g_gram[i] = 0.0f;
        if (threadIdx.x == 0) g_cnt = 0u;
    }

    const int ph = bid & 7;
    const int pd = (bid >> 3) & 7;
    const int c  = (bid >> 6) & 31;
    const int b  = (bid >> 11) & 1;
    const int t  = bid >> 12;

    const float* __restrict__ in = (t == 0) ? p1 : p2;

    const int tid = threadIdx.x;
    const int f4  = tid % 24;   // w = 4*f4
    const int rs  = tid / 24;   // d chunk [3rs, 3rs+3)

    const float* __restrict__ base =
        in + ((size_t)(b * CH + c)) * (DIM * DIM * DIM)
           + (size_t)(pd * BLK + 3 * rs) * (DIM * DIM)
           + (size_t)ph * BLK * DIM
           + f4 * 4;

    float acc = 0.0f;
    #pragma unroll
    for (int d2 = 0; d2 < 3; ++d2) {
        #pragma unroll
        for (int h = 0; h < 12; ++h) {
            const float4 v = __ldcs(reinterpret_cast<const float4*>(
                base + d2 * (DIM * DIM) + h * DIM));
            acc += (v.x + v.y) + (v.z + v.w);
        }
    }

    __shared__ float sh[96];
    sh[tid] = acc;
    __syncthreads();

    if (tid < 8) {
        float s = 0.0f;
        #pragma unroll
        for (int r2 = 0; r2 < 4; ++r2)
            #pragma unroll
            for (int j = 0; j < 3; ++j)
                s += sh[r2 * 24 + tid * 3 + j];
        const int l = pd * 64 + ph * 8 + tid;
        g_pooled[(((size_t)t * BATCH + b) * LTOK + l) * CH + c] =
            s * (1.0f / (BLK * BLK * BLK));
    }
}

// ---------------------------------------------------------------------------
// Kernel 2: Gram accumulation + fused finalize, 16-token chunks.
// 64 blocks = 2 batches x 32 chunks, 256 threads each.
// Load+normalize: 8 threads per token-side (one float4 of 4 channels each),
// 3 shfl-xor for the norm, normalized scatter to channel-major smem
// (stride 17: store banks 4*sub+l all distinct; gram Q reads 2*tj+l
// distinct, P reads broadcast). Gram: 2x2 register tiles over 16 l's
// (aa+ab fused sharing P loads), 12 atomicAdds into the global Gram.
// Counter-elected last block reduces +/-||G||^2 and writes the scalar.
// ---------------------------------------------------------------------------
#define LSTR3 17
#define CTOK  16
#define SIM_BLOCKS 64

__global__ __launch_bounds__(256) void sim_kernel(float* __restrict__ out)
{
    __shared__ float sh[2 * CH * LSTR3];   // [t][c][l] : 4.4 KB
    __shared__ float wsum[8];
    __shared__ int is_last;

    const int b     = blockIdx.x >> 5;    // 0..1
    const int chunk = blockIdx.x & 31;    // 0..31
    const int l0    = chunk * CTOK;
    const int tid   = threadIdx.x;

    // ---- fused load + normalize: 32 token-sides, 8 threads each ----------
    {
        const int tok = tid >> 3;          // 0..31
        const int sub = tid & 7;           // channels [4*sub, 4*sub+4)
        const int tt  = tok >> 4;          // tensor
        const int l   = tok & 15;

        const float* __restrict__ src =
            g_pooled + (((size_t)tt * BATCH + b) * LTOK + l0 + l) * CH + sub * 4;
        const float4 v = __ldcg(reinterpret_cast<const float4*>(src));

        float s = v.x * v.x + v.y * v.y + v.z * v.z + v.w * v.w;
        s += __shfl_xor_sync(0xFFFFFFFFu, s, 1);
        s += __shfl_xor_sync(0xFFFFFFFFu, s, 2);
        s += __shfl_xor_sync(0xFFFFFFFFu, s, 4);
        const float r = rsqrtf(fmaxf(s, EPS));

        float* __restrict__ dst = sh + tt * CH * LSTR3 + (sub * 4) * LSTR3 + l;
        dst[0 * LSTR3] = v.x * r;  dst[1 * LSTR3] = v.y * r;
        dst[2 * LSTR3] = v.z * r;  dst[3 * LSTR3] = v.w * r;
    }
    __syncthreads();

    // ---- 2x2 register-tiled Grams over this chunk's 16 l's ---------------
    const int tj = tid & 15;
    const int ti = tid >> 4;
    const float* __restrict__ A = sh;
    const float* __restrict__ B = sh + CH * LSTR3;
    float* __restrict__ dstb = g_gram + ((size_t)b * 3) * (CH * CH);

    // fused: Gaa (A,A) and Gab (A,B) share P = A row loads
    {
        float s00 = 0, s01 = 0, s10 = 0, s11 = 0;   // aa
        float x00 = 0, x01 = 0, x10 = 0, x11 = 0;   // ab
        #pragma unroll
        for (int l = 0; l < CTOK; ++l) {
            const float p0  = A[(2 * ti)     * LSTR3 + l];
            const float p1  = A[(2 * ti + 1) * LSTR3 + l];
            const float qa0 = A[(2 * tj)     * LSTR3 + l];
            const float qa1 = A[(2 * tj + 1) * LSTR3 + l];
            const float qb0 = B[(2 * tj)     * LSTR3 + l];
            const float qb1 = B[(2 * tj + 1) * LSTR3 + l];
            s00 += p0 * qa0;  s01 += p0 * qa1;
            s10 += p1 * qa0;  s11 += p1 * qa1;
            x00 += p0 * qb0;  x01 += p0 * qb1;
            x10 += p1 * qb0;  x11 += p1 * qb1;
        }
        float* d0 = dstb;                 // aa
        float* d2 = dstb + 2 * CH * CH;   // ab
        atomicAdd(&d0[(2 * ti)     * CH + 2 * tj],     s00);
        atomicAdd(&d0[(2 * ti)     * CH + 2 * tj + 1], s01);
        atomicAdd(&d0[(2 * ti + 1) * CH + 2 * tj],     s10);
        atomicAdd(&d0[(2 * ti + 1) * CH + 2 * tj + 1], s11);
        atomicAdd(&d2[(2 * ti)     * CH + 2 * tj],     x00);
        atomicAdd(&d2[(2 * ti)     * CH + 2 * tj + 1], x01);
        atomicAdd(&d2[(2 * ti + 1) * CH + 2 * tj],     x10);
        atomicAdd(&d2[(2 * ti + 1) * CH + 2 * tj + 1], x11);
    }
    // Gbb (B,B)
    {
        float s00 = 0, s01 = 0, s10 = 0, s11 = 0;
        #pragma unroll
        for (int l = 0; l < CTOK; ++l) {
            const float p0 = B[(2 * ti)     * LSTR3 + l];
            const float p1 = B[(2 * ti + 1) * LSTR3 + l];
            const float q0 = B[(2 * tj)     * LSTR3 + l];
            const float q1 = B[(2 * tj + 1) * LSTR3 + l];
            s00 += p0 * q0;  s01 += p0 * q1;
            s10 += p1 * q0;  s11 += p1 * q1;
        }
        float* d1 = dstb + CH * CH;
        atomicAdd(&d1[(2 * ti)     * CH + 2 * tj],     s00);
        atomicAdd(&d1[(2 * ti)     * CH + 2 * tj + 1], s01);
        atomicAdd(&d1[(2 * ti + 1) * CH + 2 * tj],     s10);
        atomicAdd(&d1[(2 * ti + 1) * CH + 2 * tj + 1], s11);
    }

    // ---- completion counter -> last block finalizes -----------------------
    __threadfence();
    __syncthreads();
    if (tid == 0) {
        const unsigned int old = atomicAdd(&g_cnt, 1u);
        is_last = (old == SIM_BLOCKS - 1) ? 1 : 0;
    }
    __syncthreads();
    if (!is_last) return;

    __threadfence();   // acquire all gram atomics

    // loss = sum_b ( ||Gaa||^2 + ||Gbb||^2 - 2||Gab||^2 ) / (L^2 * B)
    float local = 0.0f;
    const float4* __restrict__ gv = reinterpret_cast<const float4*>(g_gram);
    for (int i4 = tid; i4 < (BATCH * 3 * CH * CH) / 4; i4 += 256) {
        const int g = (i4 >> 8) % 3;           // 256 float4 per gram
        const float w = (g == 2) ? -2.0f : 1.0f;
        const float4 v = __ldcg(&gv[i4]);
        local += w * (v.x * v.x + v.y * v.y + v.z * v.z + v.w * v.w);
    }
    #pragma unroll
    for (int off = 16; off > 0; off >>= 1)
        local += __shfl_xor_sync(0xFFFFFFFFu, local, off);
    if ((tid & 31) == 0) wsum[tid >> 5] = local;
    __syncthreads();
    if (tid == 0) {
        float s = 0.0f;
        #pragma unroll
        for (int i = 0; i < 8; ++i) s += wsum[i];
        out[0] = s * (1.0f / ((float)LTOK * (float)LTOK * (float)BATCH));
    }
}

// ---------------------------------------------------------------------------
extern "C" void kernel_launch(void* const* d_in, const int* in_sizes, int n_in,
                              void* d_out, int out_size)
{
    const float* p1 = (const float*)d_in[0];
    const float* p2 = (const float*)d_in[1];
    float* out = (float*)d_out;

    pool_kernel<<<8192, 96>>>(p1, p2);   // 2*2*32*8*8 blocks
    sim_kernel<<<SIM_BLOCKS, 256>>>(out);
}